// round 15
// baseline (speedup 1.0000x reference)
#include <cuda_runtime.h>
#include <cuda_fp16.h>
#include <cstddef>
#include <cstdint>

#define EMB 384
#define DESK 768
#define NMAX 50000
#define EMAX 800000

// Scratch (static __device__ arrays; no allocation anywhere)
__device__ __half g_h0[(size_t)NMAX * EMB];    // feature/agg buffer 0
__device__ __half g_h1[(size_t)NMAX * EMB];    // feature/agg buffer 1
__device__ __half g_h2[(size_t)NMAX * EMB];    // conv message buffer
__device__ __half g_wT[4][EMB * EMB];          // transposed fp16 weights [n][k]
__device__ __half g_wTdes[128 * DESK];         // transposed fp16 W_des [n][k]
__device__ float  g_dinv[NMAX];
__device__ int    g_deg[NMAX];
__device__ int    g_rowptr[NMAX + 1];
__device__ int    g_cnt[NMAX];
__device__ int    g_csr[EMAX];
__device__ int    g_bsum[1024];

template <int SEL>
__device__ __forceinline__ __half* HBUF() {
    if constexpr (SEL == 0) return g_h0;
    else if constexpr (SEL == 1) return g_h1;
    else return g_h2;
}

__device__ __forceinline__ float leaky01(float x) { return x > 0.f ? x : 0.01f * x; }

__device__ __forceinline__ void cp_async16(void* smem_dst, const void* gsrc, int src_bytes) {
    uint32_t saddr = (uint32_t)__cvta_generic_to_shared(smem_dst);
    asm volatile("cp.async.cg.shared.global [%0], [%1], 16, %2;"
                 :: "r"(saddr), "l"(gsrc), "r"(src_bytes) : "memory");
}
#define CP_COMMIT() asm volatile("cp.async.commit_group;" ::: "memory")
#define CP_WAIT1()  asm volatile("cp.async.wait_group 1;" ::: "memory")
#define CP_WAIT0()  asm volatile("cp.async.wait_group 0;" ::: "memory")

__device__ __forceinline__ void mma_f16(
    float& c0, float& c1, float& c2, float& c3,
    uint32_t a0, uint32_t a1, uint32_t a2, uint32_t a3,
    uint32_t b0, uint32_t b1)
{
    asm volatile(
        "mma.sync.aligned.m16n8k16.row.col.f32.f16.f16.f32 "
        "{%0,%1,%2,%3}, {%4,%5,%6,%7}, {%8,%9}, {%0,%1,%2,%3};"
        : "+f"(c0), "+f"(c1), "+f"(c2), "+f"(c3)
        : "r"(a0), "r"(a1), "r"(a2), "r"(a3), "r"(b0), "r"(b1));
}

__device__ __forceinline__ uint32_t pack2(float x, float y) {
    half2 h = __floats2half2_rn(x, y);
    return *(uint32_t*)&h;
}

// ---------------------------------------------------------------------------
// fp16 GEMM: C[M,*] = act(A[M,KD] @ W + b), A fp16 (row stride KD),
// W^T fp16 [n][KD]. BM=128, BN=128, BK=32, cp.async 3-stage pipeline with a
// SINGLE barrier per K-iteration. m16n8k16.
// FUSE_OUT: dot 128-col slice with W2 (384x2) -> atomicAdd 2 logits/row.
// ---------------------------------------------------------------------------
template <int SRC, int DST, int WIDX, int KD, int HAS_BIAS, int ACT, int FUSE_OUT>
__global__ void __launch_bounds__(256, 2) hgemm(
    const float* __restrict__ bias,
    const float* __restrict__ W2, float* __restrict__ outp, int M)
{
    const __half* __restrict__ A = HBUF<SRC>();
    const __half* __restrict__ Bt = g_wT[WIDX];

    __shared__ __half As[3][128][40];   // [m][k], row stride 80B
    __shared__ __half Bs[3][128][40];   // [n][k], row stride 80B
    __shared__ float Wo[128][2];

    const int tid = threadIdx.x;
    const int lane = tid & 31;
    const int warp = tid >> 5;
    const int warp_m = warp & 3;
    const int warp_n = warp >> 2;
    const int gid = lane >> 2;
    const int tig = lane & 3;

    const int row0 = blockIdx.y * 128;
    const int col0 = blockIdx.x * 128;

    if constexpr (FUSE_OUT) {
        if (tid < 128) {
            Wo[tid][0] = W2[(col0 + tid) * 2 + 0];
            Wo[tid][1] = W2[(col0 + tid) * 2 + 1];
        }
    }

    float c[2][8][4];
    #pragma unroll
    for (int i = 0; i < 2; i++)
        #pragma unroll
        for (int j = 0; j < 8; j++)
            #pragma unroll
            for (int q = 0; q < 4; q++) c[i][j][q] = 0.f;

    auto load_tile = [&](int kt, int buf) {
        const int k0 = kt * 32;
        #pragma unroll
        for (int i = 0; i < 2; i++) {
            int seg = tid + i * 256;
            int r = seg >> 2;
            int cf = (seg & 3) * 8;
            int gr = row0 + r;
            int grc = gr < M ? gr : (M - 1);
            cp_async16(&As[buf][r][cf], A + (size_t)grc * KD + k0 + cf,
                       gr < M ? 16 : 0);
        }
        #pragma unroll
        for (int i = 0; i < 2; i++) {
            int seg = tid + i * 256;
            int r = seg >> 2;
            int cf = (seg & 3) * 8;
            cp_async16(&Bs[buf][r][cf], Bt + (size_t)(col0 + r) * KD + k0 + cf, 16);
        }
    };

    auto compute = [&](int buf) {
        #pragma unroll
        for (int ks = 0; ks < 2; ks++) {
            const int kb = ks * 16 + 2 * tig;
            uint32_t af[2][4], bf[8][2];
            #pragma unroll
            for (int tm = 0; tm < 2; tm++) {
                int mrow = warp_m * 32 + tm * 16 + gid;
                af[tm][0] = *(const uint32_t*)&As[buf][mrow][kb];
                af[tm][1] = *(const uint32_t*)&As[buf][mrow + 8][kb];
                af[tm][2] = *(const uint32_t*)&As[buf][mrow][kb + 8];
                af[tm][3] = *(const uint32_t*)&As[buf][mrow + 8][kb + 8];
            }
            #pragma unroll
            for (int tn = 0; tn < 8; tn++) {
                int ncol = warp_n * 64 + tn * 8 + gid;
                bf[tn][0] = *(const uint32_t*)&Bs[buf][ncol][kb];
                bf[tn][1] = *(const uint32_t*)&Bs[buf][ncol][kb + 8];
            }
            #pragma unroll
            for (int tm = 0; tm < 2; tm++)
                #pragma unroll
                for (int tn = 0; tn < 8; tn++)
                    mma_f16(c[tm][tn][0], c[tm][tn][1], c[tm][tn][2], c[tm][tn][3],
                            af[tm][0], af[tm][1], af[tm][2], af[tm][3],
                            bf[tn][0], bf[tn][1]);
        }
    };

    const int KT = KD / 32;          // 12 (or 24 for des path) >= 2
    load_tile(0, 0); CP_COMMIT();
    load_tile(1, 1); CP_COMMIT();
    for (int kt = 0; kt < KT; kt++) {
        if (kt + 1 < KT) CP_WAIT1(); else CP_WAIT0();   // tile kt ready (this thread)
        __syncthreads();                                // publish tile kt; compute(kt-1) done
        if (kt + 2 < KT) {
            load_tile(kt + 2, (kt + 2) % 3);            // overwrites tile kt-1's buffer: safe
            CP_COMMIT();
        }
        compute(kt % 3);
        // no trailing barrier: next iteration's barrier protects buffer reuse
    }
    __syncthreads();

    if constexpr (FUSE_OUT) {
        #pragma unroll
        for (int tm = 0; tm < 2; tm++) {
            #pragma unroll
            for (int h = 0; h < 2; h++) {
                int gr = row0 + warp_m * 32 + tm * 16 + gid + h * 8;
                float s0 = 0.f, s1 = 0.f;
                #pragma unroll
                for (int tn = 0; tn < 8; tn++) {
                    int lc = warp_n * 64 + tn * 8 + 2 * tig;
                    float v0 = c[tm][tn][h * 2 + 0];
                    float v1 = c[tm][tn][h * 2 + 1];
                    if (HAS_BIAS) { v0 += bias[col0 + lc]; v1 += bias[col0 + lc + 1]; }
                    if (ACT) { v0 = leaky01(v0); v1 = leaky01(v1); }
                    s0 += v0 * Wo[lc][0] + v1 * Wo[lc + 1][0];
                    s1 += v0 * Wo[lc][1] + v1 * Wo[lc + 1][1];
                }
                s0 += __shfl_down_sync(0xFFFFFFFFu, s0, 1, 4);
                s0 += __shfl_down_sync(0xFFFFFFFFu, s0, 2, 4);
                s1 += __shfl_down_sync(0xFFFFFFFFu, s1, 1, 4);
                s1 += __shfl_down_sync(0xFFFFFFFFu, s1, 2, 4);
                if (tig == 0 && gr < M) {
                    atomicAdd(outp + (size_t)gr * 2 + 0, s0);
                    atomicAdd(outp + (size_t)gr * 2 + 1, s1);
                }
            }
        }
    } else {
        __half* __restrict__ C = HBUF<DST>();
        #pragma unroll
        for (int tm = 0; tm < 2; tm++) {
            int rbase = row0 + warp_m * 32 + tm * 16 + gid;
            #pragma unroll
            for (int tn = 0; tn < 8; tn++) {
                int gc = col0 + warp_n * 64 + tn * 8 + 2 * tig;
                float bx = 0.f, by = 0.f;
                if (HAS_BIAS) { bx = bias[gc]; by = bias[gc + 1]; }
                #pragma unroll
                for (int h = 0; h < 2; h++) {
                    int gr = rbase + h * 8;
                    if (gr >= M) continue;
                    float v0 = c[tm][tn][h * 2 + 0] + bx;
                    float v1 = c[tm][tn][h * 2 + 1] + by;
                    if (ACT) { v0 = leaky01(v0); v1 = leaky01(v1); }
                    *(half2*)(C + (size_t)gr * EMB + gc) = __floats2half2_rn(v0, v1);
                }
            }
        }
    }
}

// ---------------------------------------------------------------------------
// des GEMM: fp32 A LDG -> fp16 regs -> STS; B via cp.async (R13-proven).
// ---------------------------------------------------------------------------
__global__ void __launch_bounds__(256, 2) hgemm_des(
    const float* __restrict__ A, const float* __restrict__ bias, int M)
{
    __shared__ __half As[2][128][40];
    __shared__ __half Bs[2][128][40];

    const int tid = threadIdx.x;
    const int lane = tid & 31;
    const int warp = tid >> 5;
    const int warp_m = warp & 3;
    const int warp_n = warp >> 2;
    const int gid = lane >> 2;
    const int tig = lane & 3;
    const int row0 = blockIdx.y * 128;

    const int a_row = tid >> 1;
    const int a_col = (tid & 1) * 16;
    const int a_gr = row0 + a_row;
    const int a_grc = a_gr < M ? a_gr : (M - 1);
    const float4* a_src = (const float4*)(A + (size_t)a_grc * DESK + a_col);

    float4 ar[4];
    auto ldg_a = [&](int kt) {
        const int s4 = kt * 8;
        ar[0] = a_src[s4 + 0];
        ar[1] = a_src[s4 + 1];
        ar[2] = a_src[s4 + 2];
        ar[3] = a_src[s4 + 3];
    };
    auto sts_a = [&](int buf) {
        uint4 u0, u1;
        u0.x = pack2(ar[0].x, ar[0].y); u0.y = pack2(ar[0].z, ar[0].w);
        u0.z = pack2(ar[1].x, ar[1].y); u0.w = pack2(ar[1].z, ar[1].w);
        u1.x = pack2(ar[2].x, ar[2].y); u1.y = pack2(ar[2].z, ar[2].w);
        u1.z = pack2(ar[3].x, ar[3].y); u1.w = pack2(ar[3].z, ar[3].w);
        *(uint4*)&As[buf][a_row][a_col] = u0;
        *(uint4*)&As[buf][a_row][a_col + 8] = u1;
    };
    auto load_b = [&](int kt, int buf) {
        const int k0 = kt * 32;
        #pragma unroll
        for (int i = 0; i < 2; i++) {
            int seg = tid + i * 256;
            int r = seg >> 2;
            int cf = (seg & 3) * 8;
            cp_async16(&Bs[buf][r][cf], g_wTdes + (size_t)r * DESK + k0 + cf, 16);
        }
    };

    float c[2][8][4];
    #pragma unroll
    for (int i = 0; i < 2; i++)
        #pragma unroll
        for (int j = 0; j < 8; j++)
            #pragma unroll
            for (int q = 0; q < 4; q++) c[i][j][q] = 0.f;

    auto compute = [&](int buf) {
        #pragma unroll
        for (int ks = 0; ks < 2; ks++) {
            const int kb = ks * 16 + 2 * tig;
            uint32_t af[2][4], bf[8][2];
            #pragma unroll
            for (int tm = 0; tm < 2; tm++) {
                int mrow = warp_m * 32 + tm * 16 + gid;
                af[tm][0] = *(const uint32_t*)&As[buf][mrow][kb];
                af[tm][1] = *(const uint32_t*)&As[buf][mrow + 8][kb];
                af[tm][2] = *(const uint32_t*)&As[buf][mrow][kb + 8];
                af[tm][3] = *(const uint32_t*)&As[buf][mrow + 8][kb + 8];
            }
            #pragma unroll
            for (int tn = 0; tn < 8; tn++) {
                int ncol = warp_n * 64 + tn * 8 + gid;
                bf[tn][0] = *(const uint32_t*)&Bs[buf][ncol][kb];
                bf[tn][1] = *(const uint32_t*)&Bs[buf][ncol][kb + 8];
            }
            #pragma unroll
            for (int tm = 0; tm < 2; tm++)
                #pragma unroll
                for (int tn = 0; tn < 8; tn++)
                    mma_f16(c[tm][tn][0], c[tm][tn][1], c[tm][tn][2], c[tm][tn][3],
                            af[tm][0], af[tm][1], af[tm][2], af[tm][3],
                            bf[tn][0], bf[tn][1]);
        }
    };

    const int KT = DESK / 32;   // 24
    ldg_a(0);
    load_b(0, 0);
    CP_COMMIT();
    for (int kt = 0; kt < KT; kt++) {
        int buf = kt & 1;
        if (kt + 1 < KT) { load_b(kt + 1, buf ^ 1); CP_COMMIT(); }
        sts_a(buf);
        if (kt + 1 < KT) { ldg_a(kt + 1); CP_WAIT1(); }
        else             { CP_WAIT0(); }
        __syncthreads();
        compute(buf);
        __syncthreads();
    }

    #pragma unroll
    for (int tm = 0; tm < 2; tm++) {
        int rbase = row0 + warp_m * 32 + tm * 16 + gid;
        #pragma unroll
        for (int tn = 0; tn < 8; tn++) {
            int gc = warp_n * 64 + tn * 8 + 2 * tig;
            float bx = bias[gc], by = bias[gc + 1];
            #pragma unroll
            for (int h = 0; h < 2; h++) {
                int gr = rbase + h * 8;
                if (gr >= M) continue;
                float v0 = leaky01(c[tm][tn][h * 2 + 0] + bx);
                float v1 = leaky01(c[tm][tn][h * 2 + 1] + by);
                *(half2*)(g_h0 + (size_t)gr * EMB + gc) = __floats2half2_rn(v0, v1);
            }
        }
    }
}

// ---------------------------------------------------------------------------
// Transposes: 4 square weights -> g_wT (grid 12,12,4); W_des -> g_wTdes.
// ---------------------------------------------------------------------------
__global__ void wt_kernel(
    const float* __restrict__ W0, const float* __restrict__ W1,
    const float* __restrict__ W2, const float* __restrict__ W3)
{
    __shared__ float t[32][33];
    const float* W = (blockIdx.z == 0) ? W0 : (blockIdx.z == 1) ? W1
                     : (blockIdx.z == 2) ? W2 : W3;
    int tx = threadIdx.x, ty = threadIdx.y;
    t[ty][tx] = W[(blockIdx.y * 32 + ty) * EMB + blockIdx.x * 32 + tx];
    __syncthreads();
    int nn = blockIdx.x * 32 + ty;
    int kk = blockIdx.y * 32 + tx;
    g_wT[blockIdx.z][nn * EMB + kk] = __float2half(t[tx][ty]);
}

__global__ void wt_des_kernel(const float* __restrict__ W)
{
    __shared__ float t[32][33];
    int tx = threadIdx.x, ty = threadIdx.y;
    t[ty][tx] = W[(blockIdx.y * 32 + ty) * 128 + blockIdx.x * 32 + tx];
    __syncthreads();
    int nn = blockIdx.x * 32 + ty;
    int kk = blockIdx.y * 32 + tx;
    g_wTdes[nn * DESK + kk] = __float2half(t[tx][ty]);
}

// ---------------------------------------------------------------------------
// num/cat feature linears (K=4, K=3) -> g_h0 columns [128:256), [256:384)
// ---------------------------------------------------------------------------
__global__ void numcat_kernel(
    const float* __restrict__ np_, const float* __restrict__ cp,
    const float* __restrict__ Wn, const float* __restrict__ bn,
    const float* __restrict__ Wc, const float* __restrict__ bc, int N)
{
    int i = blockIdx.x * blockDim.x + threadIdx.x;
    int node = i >> 7;
    int col = i & 127;
    if (node >= N) return;

    float s = bn[col];
    #pragma unroll
    for (int k = 0; k < 4; k++) s += np_[node * 4 + k] * Wn[k * 128 + col];
    g_h0[(size_t)node * EMB + 128 + col] = __float2half(leaky01(s));

    float t = bc[col];
    #pragma unroll
    for (int k = 0; k < 3; k++) t += cp[node * 3 + k] * Wc[k * 128 + col];
    g_h0[(size_t)node * EMB + 256 + col] = __float2half(leaky01(t));
}

// ---------------------------------------------------------------------------
// prep: deg=0, cnt=0, out=bias. Then count/scan/fill build CSR (stream B).
// ---------------------------------------------------------------------------
__global__ void prep_kernel(float* __restrict__ out, const float* __restrict__ b, int N)
{
    int i = blockIdx.x * blockDim.x + threadIdx.x;
    if (i < N) {
        g_deg[i] = 0;
        g_cnt[i] = 0;
        out[(size_t)i * 2 + 0] = b[0];
        out[(size_t)i * 2 + 1] = b[1];
    }
}

__global__ void count_deg(const int* __restrict__ ei, int E)
{
    int e = blockIdx.x * blockDim.x + threadIdx.x;
    if (e < E) atomicAdd(&g_deg[ei[E + e]], 1);
}

__global__ void scan_pass1(int N)
{
    __shared__ int red[256];
    int t = threadIdx.x;
    int i = blockIdx.x * 256 + t;
    int d = (i < N) ? g_deg[i] : 0;
    if (i < N) g_dinv[i] = rsqrtf((float)d + 1.0f);
    red[t] = d;
    __syncthreads();
    #pragma unroll
    for (int off = 128; off > 0; off >>= 1) {
        if (t < off) red[t] += red[t + off];
        __syncthreads();
    }
    if (t == 0) g_bsum[blockIdx.x] = red[0];
}

__global__ void __launch_bounds__(1024) scan_pass2(int NB)
{
    __shared__ int s[1024];
    int t = threadIdx.x;
    int v = (t < NB) ? g_bsum[t] : 0;
    s[t] = v;
    __syncthreads();
    #pragma unroll
    for (int off = 1; off < 1024; off <<= 1) {
        int u = (t >= off) ? s[t - off] : 0;
        __syncthreads();
        s[t] += u;
        __syncthreads();
    }
    if (t < NB) g_bsum[t] = s[t] - v;
}

__global__ void scan_pass3(int N)
{
    __shared__ int s[256];
    int t = threadIdx.x;
    int i = blockIdx.x * 256 + t;
    int d = (i < N) ? g_deg[i] : 0;
    s[t] = d;
    __syncthreads();
    #pragma unroll
    for (int off = 1; off < 256; off <<= 1) {
        int u = (t >= off) ? s[t - off] : 0;
        __syncthreads();
        s[t] += u;
        __syncthreads();
    }
    int base = g_bsum[blockIdx.x];
    if (i < N) {
        g_rowptr[i] = base + s[t] - d;
        if (i == N - 1) g_rowptr[N] = base + s[t];
    }
}

__global__ void fill_csr(const int* __restrict__ ei, int E)
{
    int e = blockIdx.x * blockDim.x + threadIdx.x;
    if (e >= E) return;
    int d = ei[E + e];
    int pos = g_rowptr[d] + atomicAdd(&g_cnt[d], 1);
    g_csr[pos] = ei[e];
}

// ---------------------------------------------------------------------------
// GCN gather: fp16 messages (g_h2) -> fp16 agg, fp32 accumulation.
// One warp per node, 8-edge unrolled (MLP).
// ---------------------------------------------------------------------------
__device__ __forceinline__ void fmah(float4& a, const uint2 u, float n) {
    const half2* h = (const half2*)&u;
    float2 f0 = __half22float2(h[0]);
    float2 f1 = __half22float2(h[1]);
    a.x = fmaf(f0.x, n, a.x);
    a.y = fmaf(f0.y, n, a.y);
    a.z = fmaf(f1.x, n, a.z);
    a.w = fmaf(f1.y, n, a.w);
}

__device__ __forceinline__ uint2 packf4(const float4 a) {
    half2 lo = __floats2half2_rn(a.x, a.y);
    half2 hi = __floats2half2_rn(a.z, a.w);
    uint2 u;
    u.x = *(const uint32_t*)&lo;
    u.y = *(const uint32_t*)&hi;
    return u;
}

template <int DST>
__global__ void gcn_gather_h(const float* __restrict__ bias, int N)
{
    const __half* __restrict__ xw = g_h2;
    __half* __restrict__ agg = HBUF<DST>();

    int w = (blockIdx.x * blockDim.x + threadIdx.x) >> 5;
    int lane = threadIdx.x & 31;
    if (w >= N) return;

    float din = g_dinv[w];
    float self = din * din;

    const uint2* xr = (const uint2*)(xw + (size_t)w * EMB);
    const float4* bi = (const float4*)bias;

    float4 a0 = bi[lane], a1 = bi[lane + 32], a2 = bi[lane + 64];
    fmah(a0, xr[lane], self);
    fmah(a1, xr[lane + 32], self);
    fmah(a2, xr[lane + 64], self);

    int p = g_rowptr[w];
    const int pe = g_rowptr[w + 1];

    // 8-edge unroll for MLP on the L2-latency chains
    for (; p + 7 < pe; p += 8) {
        int s[8];
        #pragma unroll
        for (int e = 0; e < 8; e++) s[e] = g_csr[p + e];
        float nn[8];
        #pragma unroll
        for (int e = 0; e < 8; e++) nn[e] = g_dinv[s[e]] * din;
        uint2 v[8][3];
        #pragma unroll
        for (int e = 0; e < 8; e++) {
            const uint2* x = (const uint2*)(xw + (size_t)s[e] * EMB);
            v[e][0] = x[lane]; v[e][1] = x[lane + 32]; v[e][2] = x[lane + 64];
        }
        #pragma unroll
        for (int e = 0; e < 8; e++) {
            fmah(a0, v[e][0], nn[e]);
            fmah(a1, v[e][1], nn[e]);
            fmah(a2, v[e][2], nn[e]);
        }
    }
    for (; p + 1 < pe; p += 2) {
        int s0 = g_csr[p], s1 = g_csr[p + 1];
        float n0 = g_dinv[s0] * din;
        float n1 = g_dinv[s1] * din;
        const uint2* x0 = (const uint2*)(xw + (size_t)s0 * EMB);
        const uint2* x1 = (const uint2*)(xw + (size_t)s1 * EMB);
        uint2 v00 = x0[lane], v01 = x0[lane + 32], v02 = x0[lane + 64];
        uint2 v10 = x1[lane], v11 = x1[lane + 32], v12 = x1[lane + 64];
        fmah(a0, v00, n0); fmah(a1, v01, n0); fmah(a2, v02, n0);
        fmah(a0, v10, n1); fmah(a1, v11, n1); fmah(a2, v12, n1);
    }
    if (p < pe) {
        int s0 = g_csr[p];
        float n0 = g_dinv[s0] * din;
        const uint2* x0 = (const uint2*)(xw + (size_t)s0 * EMB);
        fmah(a0, x0[lane], n0);
        fmah(a1, x0[lane + 32], n0);
        fmah(a2, x0[lane + 64], n0);
    }

    uint2* ar = (uint2*)(agg + (size_t)w * EMB);
    ar[lane] = packf4(a0);
    ar[lane + 32] = packf4(a1);
    ar[lane + 64] = packf4(a2);
}

// ---------------------------------------------------------------------------
// Launcher — kernel launches only. Fork/join: CSR chain on a side stream
// overlaps the feature-embedding GEMM chain; join before the first gather.
// ---------------------------------------------------------------------------
extern "C" void kernel_launch(void* const* d_in, const int* in_sizes, int n_in,
                              void* d_out, int out_size)
{
    const float* des = (const float*)d_in[0];
    // d_in[1] = tweet — unused by the reference model
    const float* np_ = (const float*)d_in[2];
    const float* cp  = (const float*)d_in[3];
    const int*   ei  = (const int*)d_in[4];
    const float* W_des = (const float*)d_in[5];  const float* b_des = (const float*)d_in[6];
    const float* W_num = (const float*)d_in[7];  const float* b_num = (const float*)d_in[8];
    const float* W_cat = (const float*)d_in[9];  const float* b_cat = (const float*)d_in[10];
    const float* W_in  = (const float*)d_in[11]; const float* b_in  = (const float*)d_in[12];
    const float* W_g1  = (const float*)d_in[13]; const float* b_g1  = (const float*)d_in[14];
    const float* W_g2  = (const float*)d_in[15]; const float* b_g2  = (const float*)d_in[16];
    const float* W_o1  = (const float*)d_in[17]; const float* b_o1  = (const float*)d_in[18];
    const float* W_o2  = (const float*)d_in[19]; const float* b_o2  = (const float*)d_in[20];

    const int N = in_sizes[0] / DESK;
    const int E = in_sizes[4] / 2;
    float* out = (float*)d_out;

    const int mb = (N + 127) / 128;
    const int NB = (N + 255) / 256;
    const int nwarpgrid = (int)(((size_t)N * 32 + 255) / 256);

    cudaStream_t s2;
    cudaStreamCreateWithFlags(&s2, cudaStreamNonBlocking);
    cudaEvent_t evFork, evJoin;
    cudaEventCreateWithFlags(&evFork, cudaEventDisableTiming);
    cudaEventCreateWithFlags(&evJoin, cudaEventDisableTiming);

    // --- fork: CSR chain on s2 ---
    cudaEventRecord(evFork, 0);
    cudaStreamWaitEvent(s2, evFork, 0);
    prep_kernel<<<NB, 256, 0, s2>>>(out, b_o2, N);
    count_deg<<<(E + 255) / 256, 256, 0, s2>>>(ei, E);
    scan_pass1<<<NB, 256, 0, s2>>>(N);
    scan_pass2<<<1, 1024, 0, s2>>>(NB);
    scan_pass3<<<NB, 256, 0, s2>>>(N);
    fill_csr<<<(E + 255) / 256, 256, 0, s2>>>(ei, E);
    cudaEventRecord(evJoin, s2);

    // --- main chain: weights + embedding + W_in + conv1 GEMM ---
    wt_kernel<<<dim3(12, 12, 4), dim3(32, 32)>>>(W_in, W_g1, W_g2, W_o1);
    wt_des_kernel<<<dim3(4, 24), dim3(32, 32)>>>(W_des);
    hgemm_des<<<dim3(1, mb), 256>>>(des, b_des, N);
    numcat_kernel<<<(N * 128 + 255) / 256, 256>>>(np_, cp, W_num, b_num, W_cat, b_cat, N);
    hgemm<0, 1, 0, EMB, 1, 1, 0><<<dim3(3, mb), 256>>>(b_in, nullptr, nullptr, N);
    hgemm<1, 2, 1, EMB, 0, 0, 0><<<dim3(3, mb), 256>>>(nullptr, nullptr, nullptr, N);

    // --- join: gathers need CSR + dinv (and prep'd out for the final head) ---
    cudaStreamWaitEvent(0, evJoin, 0);
    gcn_gather_h<0><<<nwarpgrid, 256>>>(b_g1, N);

    // --- GCN conv 2 ---
    hgemm<0, 2, 2, EMB, 0, 0, 0><<<dim3(3, mb), 256>>>(nullptr, nullptr, nullptr, N);
    gcn_gather_h<1><<<nwarpgrid, 256>>>(b_g2, N);

    // --- output head fused ---
    hgemm<1, 0, 3, EMB, 1, 1, 1><<<dim3(3, mb), 256>>>(b_o1, W_o2, out, N);
}

// round 17
// speedup vs baseline: 1.0623x; 1.0623x over previous
#include <cuda_runtime.h>
#include <cuda_fp16.h>
#include <cstddef>
#include <cstdint>

#define EMB 384
#define DESK 768
#define NMAX 50000
#define EMAX 800000

// Scratch (static __device__ arrays; no allocation anywhere)
__device__ __half g_h0[(size_t)NMAX * EMB];    // feature/agg buffer 0
__device__ __half g_h1[(size_t)NMAX * EMB];    // feature/agg buffer 1
__device__ __half g_h2[(size_t)NMAX * EMB];    // conv message buffer
__device__ __half g_wT[4][EMB * EMB];          // fp16 weights [n][k]: 0=W_in,1=W12,3=W_o1
__device__ __half g_wTdes[128 * DESK];         // transposed fp16 W_des [n][k]
__device__ float  g_bvec[EMB];                 // b_g1 @ W_g2
__device__ float  g_dinv[NMAX];
__device__ int    g_deg[NMAX];
__device__ int    g_rowptr[NMAX + 1];
__device__ int    g_cnt[NMAX];
__device__ int    g_csr[EMAX];
__device__ int    g_bsum[1024];

template <int SEL>
__device__ __forceinline__ __half* HBUF() {
    if constexpr (SEL == 0) return g_h0;
    else if constexpr (SEL == 1) return g_h1;
    else return g_h2;
}

__device__ __forceinline__ float leaky01(float x) { return x > 0.f ? x : 0.01f * x; }

__device__ __forceinline__ void cp_async16(void* smem_dst, const void* gsrc, int src_bytes) {
    uint32_t saddr = (uint32_t)__cvta_generic_to_shared(smem_dst);
    asm volatile("cp.async.cg.shared.global [%0], [%1], 16, %2;"
                 :: "r"(saddr), "l"(gsrc), "r"(src_bytes) : "memory");
}
#define CP_COMMIT() asm volatile("cp.async.commit_group;" ::: "memory")
#define CP_WAIT1()  asm volatile("cp.async.wait_group 1;" ::: "memory")
#define CP_WAIT0()  asm volatile("cp.async.wait_group 0;" ::: "memory")

__device__ __forceinline__ void mma_f16(
    float& c0, float& c1, float& c2, float& c3,
    uint32_t a0, uint32_t a1, uint32_t a2, uint32_t a3,
    uint32_t b0, uint32_t b1)
{
    asm volatile(
        "mma.sync.aligned.m16n8k16.row.col.f32.f16.f16.f32 "
        "{%0,%1,%2,%3}, {%4,%5,%6,%7}, {%8,%9}, {%0,%1,%2,%3};"
        : "+f"(c0), "+f"(c1), "+f"(c2), "+f"(c3)
        : "r"(a0), "r"(a1), "r"(a2), "r"(a3), "r"(b0), "r"(b1));
}

__device__ __forceinline__ uint32_t pack2(float x, float y) {
    half2 h = __floats2half2_rn(x, y);
    return *(uint32_t*)&h;
}

// ---------------------------------------------------------------------------
// fp16 GEMM: C[M,*] = act(A[M,KD] @ W + b). 3-stage cp.async, 1 barrier/iter.
// BM=128, BN=128, BK=32, m16n8k16. FUSE_OUT: fused 384x2 head into outp.
// ---------------------------------------------------------------------------
template <int SRC, int DST, int WIDX, int KD, int HAS_BIAS, int ACT, int FUSE_OUT>
__global__ void __launch_bounds__(256, 2) hgemm(
    const float* __restrict__ bias,
    const float* __restrict__ W2, float* __restrict__ outp, int M)
{
    const __half* __restrict__ A = HBUF<SRC>();
    const __half* __restrict__ Bt = g_wT[WIDX];

    __shared__ __half As[3][128][40];
    __shared__ __half Bs[3][128][40];
    __shared__ float Wo[128][2];

    const int tid = threadIdx.x;
    const int lane = tid & 31;
    const int warp = tid >> 5;
    const int warp_m = warp & 3;
    const int warp_n = warp >> 2;
    const int gid = lane >> 2;
    const int tig = lane & 3;

    const int row0 = blockIdx.y * 128;
    const int col0 = blockIdx.x * 128;

    if constexpr (FUSE_OUT) {
        if (tid < 128) {
            Wo[tid][0] = W2[(col0 + tid) * 2 + 0];
            Wo[tid][1] = W2[(col0 + tid) * 2 + 1];
        }
    }

    float c[2][8][4];
    #pragma unroll
    for (int i = 0; i < 2; i++)
        #pragma unroll
        for (int j = 0; j < 8; j++)
            #pragma unroll
            for (int q = 0; q < 4; q++) c[i][j][q] = 0.f;

    auto load_tile = [&](int kt, int buf) {
        const int k0 = kt * 32;
        #pragma unroll
        for (int i = 0; i < 2; i++) {
            int seg = tid + i * 256;
            int r = seg >> 2;
            int cf = (seg & 3) * 8;
            int gr = row0 + r;
            int grc = gr < M ? gr : (M - 1);
            cp_async16(&As[buf][r][cf], A + (size_t)grc * KD + k0 + cf,
                       gr < M ? 16 : 0);
        }
        #pragma unroll
        for (int i = 0; i < 2; i++) {
            int seg = tid + i * 256;
            int r = seg >> 2;
            int cf = (seg & 3) * 8;
            cp_async16(&Bs[buf][r][cf], Bt + (size_t)(col0 + r) * KD + k0 + cf, 16);
        }
    };

    auto compute = [&](int buf) {
        #pragma unroll
        for (int ks = 0; ks < 2; ks++) {
            const int kb = ks * 16 + 2 * tig;
            uint32_t af[2][4], bf[8][2];
            #pragma unroll
            for (int tm = 0; tm < 2; tm++) {
                int mrow = warp_m * 32 + tm * 16 + gid;
                af[tm][0] = *(const uint32_t*)&As[buf][mrow][kb];
                af[tm][1] = *(const uint32_t*)&As[buf][mrow + 8][kb];
                af[tm][2] = *(const uint32_t*)&As[buf][mrow][kb + 8];
                af[tm][3] = *(const uint32_t*)&As[buf][mrow + 8][kb + 8];
            }
            #pragma unroll
            for (int tn = 0; tn < 8; tn++) {
                int ncol = warp_n * 64 + tn * 8 + gid;
                bf[tn][0] = *(const uint32_t*)&Bs[buf][ncol][kb];
                bf[tn][1] = *(const uint32_t*)&Bs[buf][ncol][kb + 8];
            }
            #pragma unroll
            for (int tm = 0; tm < 2; tm++)
                #pragma unroll
                for (int tn = 0; tn < 8; tn++)
                    mma_f16(c[tm][tn][0], c[tm][tn][1], c[tm][tn][2], c[tm][tn][3],
                            af[tm][0], af[tm][1], af[tm][2], af[tm][3],
                            bf[tn][0], bf[tn][1]);
        }
    };

    const int KT = KD / 32;
    load_tile(0, 0); CP_COMMIT();
    load_tile(1, 1); CP_COMMIT();
    for (int kt = 0; kt < KT; kt++) {
        if (kt + 1 < KT) CP_WAIT1(); else CP_WAIT0();
        __syncthreads();
        if (kt + 2 < KT) {
            load_tile(kt + 2, (kt + 2) % 3);
            CP_COMMIT();
        }
        compute(kt % 3);
    }
    __syncthreads();

    if constexpr (FUSE_OUT) {
        #pragma unroll
        for (int tm = 0; tm < 2; tm++) {
            #pragma unroll
            for (int h = 0; h < 2; h++) {
                int gr = row0 + warp_m * 32 + tm * 16 + gid + h * 8;
                float s0 = 0.f, s1 = 0.f;
                #pragma unroll
                for (int tn = 0; tn < 8; tn++) {
                    int lc = warp_n * 64 + tn * 8 + 2 * tig;
                    float v0 = c[tm][tn][h * 2 + 0];
                    float v1 = c[tm][tn][h * 2 + 1];
                    if (HAS_BIAS) { v0 += bias[col0 + lc]; v1 += bias[col0 + lc + 1]; }
                    if (ACT) { v0 = leaky01(v0); v1 = leaky01(v1); }
                    s0 += v0 * Wo[lc][0] + v1 * Wo[lc + 1][0];
                    s1 += v0 * Wo[lc][1] + v1 * Wo[lc + 1][1];
                }
                s0 += __shfl_down_sync(0xFFFFFFFFu, s0, 1, 4);
                s0 += __shfl_down_sync(0xFFFFFFFFu, s0, 2, 4);
                s1 += __shfl_down_sync(0xFFFFFFFFu, s1, 1, 4);
                s1 += __shfl_down_sync(0xFFFFFFFFu, s1, 2, 4);
                if (tig == 0 && gr < M) {
                    atomicAdd(outp + (size_t)gr * 2 + 0, s0);
                    atomicAdd(outp + (size_t)gr * 2 + 1, s1);
                }
            }
        }
    } else {
        __half* __restrict__ C = HBUF<DST>();
        #pragma unroll
        for (int tm = 0; tm < 2; tm++) {
            int rbase = row0 + warp_m * 32 + tm * 16 + gid;
            #pragma unroll
            for (int tn = 0; tn < 8; tn++) {
                int gc = col0 + warp_n * 64 + tn * 8 + 2 * tig;
                float bx = 0.f, by = 0.f;
                if (HAS_BIAS) { bx = bias[gc]; by = bias[gc + 1]; }
                #pragma unroll
                for (int h = 0; h < 2; h++) {
                    int gr = rbase + h * 8;
                    if (gr >= M) continue;
                    float v0 = c[tm][tn][h * 2 + 0] + bx;
                    float v1 = c[tm][tn][h * 2 + 1] + by;
                    if (ACT) { v0 = leaky01(v0); v1 = leaky01(v1); }
                    *(half2*)(C + (size_t)gr * EMB + gc) = __floats2half2_rn(v0, v1);
                }
            }
        }
    }
}

// ---------------------------------------------------------------------------
// des GEMM: fp32 A LDG -> fp16 regs -> STS; B via cp.async (R13-proven).
// ---------------------------------------------------------------------------
__global__ void __launch_bounds__(256, 2) hgemm_des(
    const float* __restrict__ A, const float* __restrict__ bias, int M)
{
    __shared__ __half As[2][128][40];
    __shared__ __half Bs[2][128][40];

    const int tid = threadIdx.x;
    const int lane = tid & 31;
    const int warp = tid >> 5;
    const int warp_m = warp & 3;
    const int warp_n = warp >> 2;
    const int gid = lane >> 2;
    const int tig = lane & 3;
    const int row0 = blockIdx.y * 128;

    const int a_row = tid >> 1;
    const int a_col = (tid & 1) * 16;
    const int a_gr = row0 + a_row;
    const int a_grc = a_gr < M ? a_gr : (M - 1);
    const float4* a_src = (const float4*)(A + (size_t)a_grc * DESK + a_col);

    float4 ar[4];
    auto ldg_a = [&](int kt) {
        const int s4 = kt * 8;
        ar[0] = a_src[s4 + 0];
        ar[1] = a_src[s4 + 1];
        ar[2] = a_src[s4 + 2];
        ar[3] = a_src[s4 + 3];
    };
    auto sts_a = [&](int buf) {
        uint4 u0, u1;
        u0.x = pack2(ar[0].x, ar[0].y); u0.y = pack2(ar[0].z, ar[0].w);
        u0.z = pack2(ar[1].x, ar[1].y); u0.w = pack2(ar[1].z, ar[1].w);
        u1.x = pack2(ar[2].x, ar[2].y); u1.y = pack2(ar[2].z, ar[2].w);
        u1.z = pack2(ar[3].x, ar[3].y); u1.w = pack2(ar[3].z, ar[3].w);
        *(uint4*)&As[buf][a_row][a_col] = u0;
        *(uint4*)&As[buf][a_row][a_col + 8] = u1;
    };
    auto load_b = [&](int kt, int buf) {
        const int k0 = kt * 32;
        #pragma unroll
        for (int i = 0; i < 2; i++) {
            int seg = tid + i * 256;
            int r = seg >> 2;
            int cf = (seg & 3) * 8;
            cp_async16(&Bs[buf][r][cf], g_wTdes + (size_t)r * DESK + k0 + cf, 16);
        }
    };

    float c[2][8][4];
    #pragma unroll
    for (int i = 0; i < 2; i++)
        #pragma unroll
        for (int j = 0; j < 8; j++)
            #pragma unroll
            for (int q = 0; q < 4; q++) c[i][j][q] = 0.f;

    auto compute = [&](int buf) {
        #pragma unroll
        for (int ks = 0; ks < 2; ks++) {
            const int kb = ks * 16 + 2 * tig;
            uint32_t af[2][4], bf[8][2];
            #pragma unroll
            for (int tm = 0; tm < 2; tm++) {
                int mrow = warp_m * 32 + tm * 16 + gid;
                af[tm][0] = *(const uint32_t*)&As[buf][mrow][kb];
                af[tm][1] = *(const uint32_t*)&As[buf][mrow + 8][kb];
                af[tm][2] = *(const uint32_t*)&As[buf][mrow][kb + 8];
                af[tm][3] = *(const uint32_t*)&As[buf][mrow + 8][kb + 8];
            }
            #pragma unroll
            for (int tn = 0; tn < 8; tn++) {
                int ncol = warp_n * 64 + tn * 8 + gid;
                bf[tn][0] = *(const uint32_t*)&Bs[buf][ncol][kb];
                bf[tn][1] = *(const uint32_t*)&Bs[buf][ncol][kb + 8];
            }
            #pragma unroll
            for (int tm = 0; tm < 2; tm++)
                #pragma unroll
                for (int tn = 0; tn < 8; tn++)
                    mma_f16(c[tm][tn][0], c[tm][tn][1], c[tm][tn][2], c[tm][tn][3],
                            af[tm][0], af[tm][1], af[tm][2], af[tm][3],
                            bf[tn][0], bf[tn][1]);
        }
    };

    const int KT = DESK / 32;   // 24
    ldg_a(0);
    load_b(0, 0);
    CP_COMMIT();
    for (int kt = 0; kt < KT; kt++) {
        int buf = kt & 1;
        if (kt + 1 < KT) { load_b(kt + 1, buf ^ 1); CP_COMMIT(); }
        sts_a(buf);
        if (kt + 1 < KT) { ldg_a(kt + 1); CP_WAIT1(); }
        else             { CP_WAIT0(); }
        __syncthreads();
        compute(buf);
        __syncthreads();
    }

    #pragma unroll
    for (int tm = 0; tm < 2; tm++) {
        int rbase = row0 + warp_m * 32 + tm * 16 + gid;
        #pragma unroll
        for (int tn = 0; tn < 8; tn++) {
            int gc = warp_n * 64 + tn * 8 + 2 * tig;
            float bx = bias[gc], by = bias[gc + 1];
            #pragma unroll
            for (int h = 0; h < 2; h++) {
                int gr = rbase + h * 8;
                if (gr >= M) continue;
                float v0 = leaky01(c[tm][tn][h * 2 + 0] + bx);
                float v1 = leaky01(c[tm][tn][h * 2 + 1] + by);
                *(half2*)(g_h0 + (size_t)gr * EMB + gc) = __floats2half2_rn(v0, v1);
            }
        }
    }
}

// ---------------------------------------------------------------------------
// Weight prep.
// wt_kernel: W_in -> g_wT[0], W_o1 -> g_wT[3] (transposed fp16). Grid (12,12,2).
// w12_kernel: W12^T[n][k] = sum_m W_g1[k][m]W_g2[m][n] -> g_wT[1] (fp32 accum);
//             bvec[n] = sum_m b_g1[m]W_g2[m][n]. Grid 48 x 384 threads.
// ---------------------------------------------------------------------------
__global__ void wt_kernel(const float* __restrict__ W0, const float* __restrict__ W3)
{
    __shared__ float t[32][33];
    const float* W = (blockIdx.z == 0) ? W0 : W3;
    const int slot = (blockIdx.z == 0) ? 0 : 3;
    int tx = threadIdx.x, ty = threadIdx.y;
    t[ty][tx] = W[(blockIdx.y * 32 + ty) * EMB + blockIdx.x * 32 + tx];
    __syncthreads();
    int nn = blockIdx.x * 32 + ty;
    int kk = blockIdx.y * 32 + tx;
    g_wT[slot][nn * EMB + kk] = __float2half(t[tx][ty]);
}

__global__ void __launch_bounds__(384) w12_kernel(
    const float* __restrict__ Wg1, const float* __restrict__ Wg2,
    const float* __restrict__ bg1)
{
    const int n = threadIdx.x;              // 0..383
    const int k0 = blockIdx.x * 8;          // 48 blocks x 8 k-rows
    float acc[8] = {};
    for (int m = 0; m < EMB; m++) {
        float w2 = Wg2[m * EMB + n];
        #pragma unroll
        for (int kk = 0; kk < 8; kk++)
            acc[kk] = fmaf(Wg1[(k0 + kk) * EMB + m], w2, acc[kk]);
    }
    #pragma unroll
    for (int kk = 0; kk < 8; kk++)
        g_wT[1][n * EMB + k0 + kk] = __float2half(acc[kk]);

    if (blockIdx.x == 0) {
        float b = 0.f;
        for (int m = 0; m < EMB; m++) b = fmaf(bg1[m], Wg2[m * EMB + n], b);
        g_bvec[n] = b;
    }
}

__global__ void wt_des_kernel(const float* __restrict__ W)
{
    __shared__ float t[32][33];
    int tx = threadIdx.x, ty = threadIdx.y;
    t[ty][tx] = W[(blockIdx.y * 32 + ty) * 128 + blockIdx.x * 32 + tx];
    __syncthreads();
    int nn = blockIdx.x * 32 + ty;
    int kk = blockIdx.y * 32 + tx;
    g_wTdes[nn * DESK + kk] = __float2half(t[tx][ty]);
}

// ---------------------------------------------------------------------------
// num/cat feature linears (K=4, K=3) -> g_h0 columns [128:256), [256:384)
// ---------------------------------------------------------------------------
__global__ void numcat_kernel(
    const float* __restrict__ np_, const float* __restrict__ cp,
    const float* __restrict__ Wn, const float* __restrict__ bn,
    const float* __restrict__ Wc, const float* __restrict__ bc, int N)
{
    int i = blockIdx.x * blockDim.x + threadIdx.x;
    int node = i >> 7;
    int col = i & 127;
    if (node >= N) return;

    float s = bn[col];
    #pragma unroll
    for (int k = 0; k < 4; k++) s += np_[node * 4 + k] * Wn[k * 128 + col];
    g_h0[(size_t)node * EMB + 128 + col] = __float2half(leaky01(s));

    float t = bc[col];
    #pragma unroll
    for (int k = 0; k < 3; k++) t += cp[node * 3 + k] * Wc[k * 128 + col];
    g_h0[(size_t)node * EMB + 256 + col] = __float2half(leaky01(t));
}

// ---------------------------------------------------------------------------
// prep + CSR build (stream B)
// ---------------------------------------------------------------------------
__global__ void prep_kernel(float* __restrict__ out, const float* __restrict__ b, int N)
{
    int i = blockIdx.x * blockDim.x + threadIdx.x;
    if (i < N) {
        g_deg[i] = 0;
        g_cnt[i] = 0;
        out[(size_t)i * 2 + 0] = b[0];
        out[(size_t)i * 2 + 1] = b[1];
    }
}

__global__ void count_deg(const int* __restrict__ ei, int E)
{
    int e = blockIdx.x * blockDim.x + threadIdx.x;
    if (e < E) atomicAdd(&g_deg[ei[E + e]], 1);
}

__global__ void scan_pass1(int N)
{
    __shared__ int red[256];
    int t = threadIdx.x;
    int i = blockIdx.x * 256 + t;
    int d = (i < N) ? g_deg[i] : 0;
    if (i < N) g_dinv[i] = rsqrtf((float)d + 1.0f);
    red[t] = d;
    __syncthreads();
    #pragma unroll
    for (int off = 128; off > 0; off >>= 1) {
        if (t < off) red[t] += red[t + off];
        __syncthreads();
    }
    if (t == 0) g_bsum[blockIdx.x] = red[0];
}

__global__ void __launch_bounds__(1024) scan_pass2(int NB)
{
    __shared__ int s[1024];
    int t = threadIdx.x;
    int v = (t < NB) ? g_bsum[t] : 0;
    s[t] = v;
    __syncthreads();
    #pragma unroll
    for (int off = 1; off < 1024; off <<= 1) {
        int u = (t >= off) ? s[t - off] : 0;
        __syncthreads();
        s[t] += u;
        __syncthreads();
    }
    if (t < NB) g_bsum[t] = s[t] - v;
}

__global__ void scan_pass3(int N)
{
    __shared__ int s[256];
    int t = threadIdx.x;
    int i = blockIdx.x * 256 + t;
    int d = (i < N) ? g_deg[i] : 0;
    s[t] = d;
    __syncthreads();
    #pragma unroll
    for (int off = 1; off < 256; off <<= 1) {
        int u = (t >= off) ? s[t - off] : 0;
        __syncthreads();
        s[t] += u;
        __syncthreads();
    }
    int base = g_bsum[blockIdx.x];
    if (i < N) {
        g_rowptr[i] = base + s[t] - d;
        if (i == N - 1) g_rowptr[N] = base + s[t];
    }
}

__global__ void fill_csr(const int* __restrict__ ei, int E)
{
    int e = blockIdx.x * blockDim.x + threadIdx.x;
    if (e >= E) return;
    int d = ei[E + e];
    int pos = g_rowptr[d] + atomicAdd(&g_cnt[d], 1);
    g_csr[pos] = ei[e];
}

// ---------------------------------------------------------------------------
// GCN gather: fp16 messages HBUF<SRCB> -> fp16 agg HBUF<DST>, fp32 accum.
// MODE 0: no bias. MODE 1: += s_i*bvec + bias, s_i = sum(nn_e) + dinv_i^2.
// One warp per node, 8-edge unrolled.
// ---------------------------------------------------------------------------
__device__ __forceinline__ void fmah(float4& a, const uint2 u, float n) {
    const half2* h = (const half2*)&u;
    float2 f0 = __half22float2(h[0]);
    float2 f1 = __half22float2(h[1]);
    a.x = fmaf(f0.x, n, a.x);
    a.y = fmaf(f0.y, n, a.y);
    a.z = fmaf(f1.x, n, a.z);
    a.w = fmaf(f1.y, n, a.w);
}

__device__ __forceinline__ uint2 packf4(const float4 a) {
    half2 lo = __floats2half2_rn(a.x, a.y);
    half2 hi = __floats2half2_rn(a.z, a.w);
    uint2 u;
    u.x = *(const uint32_t*)&lo;
    u.y = *(const uint32_t*)&hi;
    return u;
}

__device__ __forceinline__ void addsb(float4& a, const float4 bv, const float4 bg, float si) {
    a.x += si * bv.x + bg.x;
    a.y += si * bv.y + bg.y;
    a.z += si * bv.z + bg.z;
    a.w += si * bv.w + bg.w;
}

template <int SRCB, int DST, int MODE>
__global__ void gcn_gather_h(const float* __restrict__ bias, int N)
{
    const __half* __restrict__ xw = HBUF<SRCB>();
    __half* __restrict__ agg = HBUF<DST>();

    int w = (blockIdx.x * blockDim.x + threadIdx.x) >> 5;
    int lane = threadIdx.x & 31;
    if (w >= N) return;

    float din = g_dinv[w];
    float self = din * din;

    const uint2* xr = (const uint2*)(xw + (size_t)w * EMB);

    float4 a0 = make_float4(0.f, 0.f, 0.f, 0.f), a1 = a0, a2 = a0;
    fmah(a0, xr[lane], self);
    fmah(a1, xr[lane + 32], self);
    fmah(a2, xr[lane + 64], self);

    float ssum = 0.f;
    int p = g_rowptr[w];
    const int pe = g_rowptr[w + 1];

    for (; p + 7 < pe; p += 8) {
        int s[8];
        #pragma unroll
        for (int e = 0; e < 8; e++) s[e] = g_csr[p + e];
        float nn[8];
        #pragma unroll
        for (int e = 0; e < 8; e++) {
            nn[e] = g_dinv[s[e]] * din;
            if (MODE == 1) ssum += nn[e];
        }
        uint2 v[8][3];
        #pragma unroll
        for (int e = 0; e < 8; e++) {
            const uint2* x = (const uint2*)(xw + (size_t)s[e] * EMB);
            v[e][0] = x[lane]; v[e][1] = x[lane + 32]; v[e][2] = x[lane + 64];
        }
        #pragma unroll
        for (int e = 0; e < 8; e++) {
            fmah(a0, v[e][0], nn[e]);
            fmah(a1, v[e][1], nn[e]);
            fmah(a2, v[e][2], nn[e]);
        }
    }
    for (; p < pe; p++) {
        int s0 = g_csr[p];
        float n0 = g_dinv[s0] * din;
        if (MODE == 1) ssum += n0;
        const uint2* x0 = (const uint2*)(xw + (size_t)s0 * EMB);
        fmah(a0, x0[lane], n0);
        fmah(a1, x0[lane + 32], n0);
        fmah(a2, x0[lane + 64], n0);
    }

    if constexpr (MODE == 1) {
        float si = ssum + self;
        const float4* bv = (const float4*)g_bvec;
        const float4* bg = (const float4*)bias;
        addsb(a0, bv[lane], bg[lane], si);
        addsb(a1, bv[lane + 32], bg[lane + 32], si);
        addsb(a2, bv[lane + 64], bg[lane + 64], si);
    }

    uint2* ar = (uint2*)(agg + (size_t)w * EMB);
    ar[lane] = packf4(a0);
    ar[lane + 32] = packf4(a1);
    ar[lane + 64] = packf4(a2);
}

// ---------------------------------------------------------------------------
// Launcher. Fork/join: W12+bvec and CSR chain on side stream overlap the
// embedding/W_in GEMM chain. Math: agg2 = A²(x1·W12) + s·(b_g1W_g2) + b_g2.
// ---------------------------------------------------------------------------
extern "C" void kernel_launch(void* const* d_in, const int* in_sizes, int n_in,
                              void* d_out, int out_size)
{
    const float* des = (const float*)d_in[0];
    // d_in[1] = tweet — unused by the reference model
    const float* np_ = (const float*)d_in[2];
    const float* cp  = (const float*)d_in[3];
    const int*   ei  = (const int*)d_in[4];
    const float* W_des = (const float*)d_in[5];  const float* b_des = (const float*)d_in[6];
    const float* W_num = (const float*)d_in[7];  const float* b_num = (const float*)d_in[8];
    const float* W_cat = (const float*)d_in[9];  const float* b_cat = (const float*)d_in[10];
    const float* W_in  = (const float*)d_in[11]; const float* b_in  = (const float*)d_in[12];
    const float* W_g1  = (const float*)d_in[13]; const float* b_g1  = (const float*)d_in[14];
    const float* W_g2  = (const float*)d_in[15]; const float* b_g2  = (const float*)d_in[16];
    const float* W_o1  = (const float*)d_in[17]; const float* b_o1  = (const float*)d_in[18];
    const float* W_o2  = (const float*)d_in[19]; const float* b_o2  = (const float*)d_in[20];

    const int N = in_sizes[0] / DESK;
    const int E = in_sizes[4] / 2;
    float* out = (float*)d_out;

    const int mb = (N + 127) / 128;
    const int NB = (N + 255) / 256;
    const int nwarpgrid = (int)(((size_t)N * 32 + 255) / 256);

    cudaStream_t s2;
    cudaStreamCreateWithFlags(&s2, cudaStreamNonBlocking);
    cudaEvent_t evFork, evW12, evJoin;
    cudaEventCreateWithFlags(&evFork, cudaEventDisableTiming);
    cudaEventCreateWithFlags(&evW12, cudaEventDisableTiming);
    cudaEventCreateWithFlags(&evJoin, cudaEventDisableTiming);

    // --- fork: W12/bvec + CSR chain on s2 ---
    cudaEventRecord(evFork, 0);
    cudaStreamWaitEvent(s2, evFork, 0);
    w12_kernel<<<48, 384, 0, s2>>>(W_g1, W_g2, b_g1);
    cudaEventRecord(evW12, s2);
    prep_kernel<<<NB, 256, 0, s2>>>(out, b_o2, N);
    count_deg<<<(E + 255) / 256, 256, 0, s2>>>(ei, E);
    scan_pass1<<<NB, 256, 0, s2>>>(N);
    scan_pass2<<<1, 1024, 0, s2>>>(NB);
    scan_pass3<<<NB, 256, 0, s2>>>(N);
    fill_csr<<<(E + 255) / 256, 256, 0, s2>>>(ei, E);
    cudaEventRecord(evJoin, s2);

    // --- main chain: weights + embedding + W_in GEMM ---
    wt_kernel<<<dim3(12, 12, 2), dim3(32, 32)>>>(W_in, W_o1);
    wt_des_kernel<<<dim3(4, 24), dim3(32, 32)>>>(W_des);
    hgemm_des<<<dim3(1, mb), 256>>>(des, b_des, N);
    numcat_kernel<<<(N * 128 + 255) / 256, 256>>>(np_, cp, W_num, b_num, W_cat, b_cat, N);
    hgemm<0, 1, 0, EMB, 1, 1, 0><<<dim3(3, mb), 256>>>(b_in, nullptr, nullptr, N);  // x1 -> h1

    // --- combined conv GEMM: M = x1 @ W12 -> h2 (needs W12) ---
    cudaStreamWaitEvent(0, evW12, 0);
    hgemm<1, 2, 1, EMB, 0, 0, 0><<<dim3(3, mb), 256>>>(nullptr, nullptr, nullptr, N);

    // --- double gather (needs CSR): t = A·M -> h0 ; agg2 = A·t + s·bvec + b_g2 -> h1 ---
    cudaStreamWaitEvent(0, evJoin, 0);
    gcn_gather_h<2, 0, 0><<<nwarpgrid, 256>>>(nullptr, N);
    gcn_gather_h<0, 1, 1><<<nwarpgrid, 256>>>(b_g2, N);

    // --- output head fused: out = leaky(agg2 @ W_o1 + b_o1) @ W_o2 + b_o2 ---
    hgemm<1, 0, 3, EMB, 1, 1, 1><<<dim3(3, mb), 256>>>(b_o1, W_o2, out, N);
}